// round 12
// baseline (speedup 1.0000x reference)
#include <cuda_runtime.h>
#include <cuda_fp16.h>
#include <cstdint>
#include <cstddef>

#define BN 1024
#define DD 768
#define TT 512
#define VV 49408

// ------------------------- static device workspace --------------------------
__device__ float g_kw[BN * TT];            // projected keywords fp32 (split-K accum)
__device__ float g_rowsum[BN];             // softmax denominators (scaled)
__device__ float g_norm[VV];               // ||emb_v|| (fp32)
__device__ __half g_kwH[BN * TT];                  // normalized kw, fp16
__device__ __half g_audioH[BN * DD];               // audio fp16
__device__ __half g_WH[DD * TT];                   // W_proj fp16 [k][n]
__device__ __half g_embH[(size_t)VV * TT];         // NORMALIZED emb [v][t], fp16
__device__ __half g_probs[(size_t)BN * VV];        // scaled probs * ||emb_v||, fp16

// ------------------------------ helpers -------------------------------------
__device__ __forceinline__ uint32_t smem_u32(const void* p) {
    uint32_t a;
    asm("{ .reg .u64 t; cvta.to.shared.u64 t, %1; cvt.u32.u64 %0, t; }"
        : "=r"(a) : "l"(p));
    return a;
}
__device__ __forceinline__ void cp16(uint32_t s, const void* g) {
    asm volatile("cp.async.cg.shared.global [%0], [%1], 16;" :: "r"(s), "l"(g));
}
__device__ __forceinline__ void ldsm4(uint32_t* r, uint32_t addr) {
    asm volatile("ldmatrix.sync.aligned.m8n8.x4.shared.b16 {%0,%1,%2,%3}, [%4];"
        : "=r"(r[0]), "=r"(r[1]), "=r"(r[2]), "=r"(r[3]) : "r"(addr));
}
__device__ __forceinline__ void ldsm4t(uint32_t* r, uint32_t addr) {
    asm volatile("ldmatrix.sync.aligned.m8n8.x4.trans.shared.b16 {%0,%1,%2,%3}, [%4];"
        : "=r"(r[0]), "=r"(r[1]), "=r"(r[2]), "=r"(r[3]) : "r"(addr));
}
__device__ __forceinline__ void mma16816(float* c, const uint32_t* a, const uint32_t* b) {
    asm volatile("mma.sync.aligned.m16n8k16.row.col.f32.f16.f16.f32 "
        "{%0,%1,%2,%3}, {%4,%5,%6,%7}, {%8,%9}, {%0,%1,%2,%3};"
        : "+f"(c[0]), "+f"(c[1]), "+f"(c[2]), "+f"(c[3])
        : "r"(a[0]), "r"(a[1]), "r"(a[2]), "r"(a[3]), "r"(b[0]), "r"(b[1]));
}
__device__ __forceinline__ uint32_t pack2h(float a, float b) {
    const __half2 h = __floats2half2_rn(a, b);
    return *reinterpret_cast<const uint32_t*>(&h);
}

// smem: A plane 128x144B; B plane: direct 128x144B, trans 64x272B (<= 18432)
#define ROWA   144
#define ROWBT  272
#define PLANE  18432
#define STAGE  (2 * PLANE)            // 36864
#define NSTAGE 2
#define SMEMSZ (NSTAGE * STAGE + 512) // 74240 -> 2 CTAs/SM

#define PSCALE 16384.f

// =============================================================================
// fp16 warp-MMA GEMM, CTA tile 128x128, BK=64, 512 thr, 16 warps, warp 32x32.
// fp32 accumulate. 2-stage cp.async double buffer.
// EPI==0: logits (A=kwH, B=embH direct) -> exp -> probs*||emb|| + rowsum atomics
// EPI==1: VQ GEMM split-K (A=probs, B=embH trans) -> (1/rowsum)*atomicAdd out
// EPI==2: projection split-K (A=audioH, B=WH trans) -> atomicAdd into g_kw
// =============================================================================
template<int EPI>
__global__ __launch_bounds__(512, 2) void mma_gemm(float* __restrict__ outf)
{
    constexpr uint32_t LDA  = (EPI == 0) ? TT : (EPI == 1) ? VV : DD;
    constexpr uint32_t LDB  = TT;                    // emb / W row stride
    constexpr int      NCHT = (EPI == 0) ? TT / 64 : (EPI == 1) ? VV / 64 : DD / 64;
    extern __shared__ char smem[];
    const uint32_t sbase = smem_u32(smem);
    const int tid = threadIdx.x;
    const int lane = tid & 31, wid = tid >> 5;      // wid 0..15
    const int warpM = wid & 3, warpN = wid >> 2;    // 4 x 4 warp grid, 32x32 tiles

    const __half *A, *B;
    int m0, n0, c0, c1;
    if (EPI == 0) {
        A = g_kwH; B = g_embH;
        m0 = blockIdx.x * 128; n0 = blockIdx.y * 128;
        c0 = 0; c1 = NCHT;
    } else {
        A = (EPI == 1) ? g_probs : g_audioH;
        B = (EPI == 1) ? g_embH  : g_WH;
        n0 = blockIdx.x * 128; m0 = blockIdx.y * 128;
        c0 = (int)(((long)NCHT * blockIdx.z) / gridDim.z);
        c1 = (int)(((long)NCHT * (blockIdx.z + 1)) / gridDim.z);
    }
    const int nch = c1 - c0;

    // per-CTA emb norms for the epilogue (EPI==0 only)
    float* sNorm = (float*)(smem + NSTAGE * STAGE);
    if (EPI == 0 && tid < 128) sNorm[tid] = g_norm[n0 + tid];

    // ---- loader thread geometry (512 threads, 32-bit offsets) ----
    const uint32_t ch   = tid & 7;           // 16B chunk within 64-elem row piece
    const uint32_t rowA = tid >> 3;          // 0..63, second half via +64
    uint32_t aOff = (uint32_t)(m0 + rowA) * LDA + (uint32_t)c0 * 64 + ch * 8;
    const uint32_t aSo = rowA * ROWA + ch * 16;
    uint32_t bOff, bSo;
    if (EPI == 0) {
        bOff = (uint32_t)(n0 + rowA) * LDB + (uint32_t)c0 * 64 + ch * 8;
        bSo  = aSo;
    } else {
        const uint32_t rb = tid >> 4, cb = tid & 15;   // 64 rows x 256B, 2 passes of 32
        bOff = ((uint32_t)c0 * 64 + rb) * LDB + (uint32_t)n0 + cb * 8;
        bSo  = rb * ROWBT + cb * 16;
    }

    auto issue = [&](uint32_t st) {
        #pragma unroll
        for (int p = 0; p < 2; p++) {
            cp16(st + aSo + p * (64 * ROWA), A + aOff + p * (64 * LDA));
            if (EPI == 0)
                cp16(st + PLANE + bSo + p * (64 * ROWA), B + bOff + p * (64 * LDB));
            else
                cp16(st + PLANE + bSo + p * (32 * ROWBT), B + bOff + p * (32 * LDB));
        }
        aOff += 64;
        bOff += (EPI == 0) ? 64 : 64 * LDB;
    };

    // ---- compute fragment smem bases ----
    const uint32_t saOff = (uint32_t)(warpM * 32 + (lane & 15)) * ROWA + ((lane >> 4) << 4);
    uint32_t sbOff;
    if (EPI == 0)
        sbOff = PLANE + (uint32_t)(warpN * 32 + (lane & 15)) * ROWA + ((lane >> 4) << 4);
    else
        sbOff = PLANE + (uint32_t)((lane & 7) + ((lane >> 4) << 3)) * ROWBT
              + (uint32_t)(warpN * 32 + ((lane >> 3) & 1) * 8) * 2;

    float acc[2][4][4];
    #pragma unroll
    for (int i = 0; i < 2; i++)
        #pragma unroll
        for (int j = 0; j < 4; j++)
            #pragma unroll
            for (int k = 0; k < 4; k++) acc[i][j][k] = 0.f;

    // ---- prologue: 2 stages in flight ----
    issue(sbase);
    asm volatile("cp.async.commit_group;" ::: "memory");
    issue(sbase + STAGE);
    asm volatile("cp.async.commit_group;" ::: "memory");

    for (int c = 0; c < nch; c++) {
        asm volatile("cp.async.wait_group 1;" ::: "memory");
        __syncthreads();
        const uint32_t st = sbase + (uint32_t)(c & 1) * STAGE;

        #pragma unroll
        for (int ks = 0; ks < 4; ks++) {
            const uint32_t ko = ks * 32;
            uint32_t a[2][4], b[2][4];
            #pragma unroll
            for (int mf = 0; mf < 2; mf++)
                ldsm4(a[mf], st + saOff + mf * (16 * ROWA) + ko);
            if (EPI == 0) {
                #pragma unroll
                for (int g = 0; g < 2; g++)
                    ldsm4(b[g], st + sbOff + g * (16 * ROWA) + ko);
            } else {
                #pragma unroll
                for (int g = 0; g < 2; g++)
                    ldsm4t(b[g], st + sbOff + ks * (16 * ROWBT) + g * 32);
            }
            #pragma unroll
            for (int mf = 0; mf < 2; mf++)
                #pragma unroll
                for (int nf = 0; nf < 4; nf++) {
                    uint32_t bf[2] = { b[nf >> 1][nf & 1],
                                       b[nf >> 1][2 + (nf & 1)] };
                    mma16816(acc[mf][nf], a[mf], bf);
                }
        }
        __syncthreads();
        if (c + 2 < nch) issue(st);
        asm volatile("cp.async.commit_group;" ::: "memory");
    }

    if (EPI == 0) {
        #pragma unroll
        for (int mf = 0; mf < 2; mf++) {
            const int r0 = m0 + warpM * 32 + mf * 16 + (lane >> 2);
            float rs0 = 0.f, rs1 = 0.f;
            #pragma unroll
            for (int nf = 0; nf < 4; nf++) {
                const int cl = warpN * 32 + nf * 8 + (lane & 3) * 2;  // local col
                const int cb = n0 + cl;
                // p = exp(10*cos - 10) * PSCALE  (scale cancels in normalization)
                const float e0 = __expf(acc[mf][nf][0] * 10.f - 10.f) * PSCALE;
                const float e1 = __expf(acc[mf][nf][1] * 10.f - 10.f) * PSCALE;
                const float e2 = __expf(acc[mf][nf][2] * 10.f - 10.f) * PSCALE;
                const float e3 = __expf(acc[mf][nf][3] * 10.f - 10.f) * PSCALE;
                rs0 += e0 + e1;  rs1 += e2 + e3;
                // fold ||emb_v|| into stored probs (GEMM2 uses normalized emb)
                const float w0 = sNorm[cl], w1 = sNorm[cl + 1];
                *(uint32_t*)&g_probs[(size_t)r0 * VV + cb] = pack2h(e0 * w0, e1 * w1);
                *(uint32_t*)&g_probs[(size_t)(r0 + 8) * VV + cb] = pack2h(e2 * w0, e3 * w1);
            }
            rs0 += __shfl_xor_sync(0xffffffffu, rs0, 1);
            rs0 += __shfl_xor_sync(0xffffffffu, rs0, 2);
            rs1 += __shfl_xor_sync(0xffffffffu, rs1, 1);
            rs1 += __shfl_xor_sync(0xffffffffu, rs1, 2);
            if ((lane & 3) == 0) {
                atomicAdd(&g_rowsum[r0],     rs0);
                atomicAdd(&g_rowsum[r0 + 8], rs1);
            }
        }
    } else {
        #pragma unroll
        for (int mf = 0; mf < 2; mf++) {
            const int r0 = m0 + warpM * 32 + mf * 16 + (lane >> 2);
            const float s0 = (EPI == 1) ? 1.f / g_rowsum[r0]     : 1.f;
            const float s1 = (EPI == 1) ? 1.f / g_rowsum[r0 + 8] : 1.f;
            #pragma unroll
            for (int nf = 0; nf < 4; nf++) {
                const int cb = n0 + warpN * 32 + nf * 8 + (lane & 3) * 2;
                atomicAdd(&outf[(size_t)r0 * TT + cb],           acc[mf][nf][0] * s0);
                atomicAdd(&outf[(size_t)r0 * TT + cb + 1],       acc[mf][nf][1] * s0);
                atomicAdd(&outf[(size_t)(r0 + 8) * TT + cb],     acc[mf][nf][2] * s1);
                atomicAdd(&outf[(size_t)(r0 + 8) * TT + cb + 1], acc[mf][nf][3] * s1);
            }
        }
    }
}

// fp32 -> fp16 streaming pack, TWO tensors in one launch (audio then W)
__global__ __launch_bounds__(512)
void pack_f16_2(const float* __restrict__ s0, __half* __restrict__ d0, int n0_4,
                const float* __restrict__ s1, __half* __restrict__ d1, int n1_4)
{
    const int total = n0_4 + n1_4;
    for (int i = blockIdx.x * blockDim.x + threadIdx.x; i < total;
         i += gridDim.x * blockDim.x) {
        const float4 v = (i < n0_4) ? ((const float4*)s0)[i]
                                    : ((const float4*)s1)[i - n0_4];
        const uint2 pk = make_uint2(pack2h(v.x, v.y), pack2h(v.z, v.w));
        if (i < n0_4) ((uint2*)d0)[i] = pk;
        else          ((uint2*)d1)[i - n0_4] = pk;
    }
}

// kw rows: add bias, L2-normalize, write fp16 (128 thr = 4 warps, 1 row/warp)
__global__ __launch_bounds__(128)
void kw_norm_pack(const float* __restrict__ bias)
{
    const int w    = (blockIdx.x * blockDim.x + threadIdx.x) >> 5;
    const int lane = threadIdx.x & 31;
    if (w >= BN) return;
    const float4* row = (const float4*)(g_kw + (size_t)w * TT);
    const float4* b4  = (const float4*)bias;
    float4 v[4];
    float ss = 0.f;
    #pragma unroll
    for (int q = 0; q < 4; q++) {
        v[q] = row[lane + 32 * q];
        const float4 bb = b4[lane + 32 * q];
        v[q].x += bb.x; v[q].y += bb.y; v[q].z += bb.z; v[q].w += bb.w;
        ss += v[q].x * v[q].x + v[q].y * v[q].y + v[q].z * v[q].z + v[q].w * v[q].w;
    }
    #pragma unroll
    for (int o = 16; o > 0; o >>= 1) ss += __shfl_xor_sync(0xffffffffu, ss, o);
    const float inv = 1.f / fmaxf(sqrtf(ss), 1e-8f);
    #pragma unroll
    for (int q = 0; q < 4; q++) {
        const int e0 = (lane + 32 * q) * 4;
        const uint2 pk = make_uint2(pack2h(v[q].x * inv, v[q].y * inv),
                                    pack2h(v[q].z * inv, v[q].w * inv));
        *(uint2*)&g_kwH[(size_t)w * TT + e0] = pk;
    }
}

// emb prep: one warp per vocab row; read fp32 once,
// write normalized fp16 (embH) + row norm (g_norm).
__global__ __launch_bounds__(512)
void emb_prep(const float* __restrict__ emb)
{
    const int w    = (blockIdx.x * blockDim.x + threadIdx.x) >> 5;
    const int lane = threadIdx.x & 31;
    if (w >= VV) return;
    const float4* row = (const float4*)(emb + (size_t)w * TT);
    float4 v[4];
    float ss = 0.f;
    #pragma unroll
    for (int q = 0; q < 4; q++) {
        v[q] = row[lane + 32 * q];
        ss += v[q].x * v[q].x + v[q].y * v[q].y + v[q].z * v[q].z + v[q].w * v[q].w;
    }
    #pragma unroll
    for (int o = 16; o > 0; o >>= 1) ss += __shfl_xor_sync(0xffffffffu, ss, o);
    const float nrm = sqrtf(ss);
    const float inv = 1.f / fmaxf(nrm, 1e-8f);
    if (lane == 0) g_norm[w] = nrm;
    #pragma unroll
    for (int q = 0; q < 4; q++) {
        const int e0 = (lane + 32 * q) * 4;
        const uint2 pk = make_uint2(pack2h(v[q].x * inv, v[q].y * inv),
                                    pack2h(v[q].z * inv, v[q].w * inv));
        *(uint2*)&g_embH[(size_t)w * TT + e0] = pk;
    }
}

// =============================================================================
extern "C" void kernel_launch(void* const* d_in, const int* in_sizes, int n_in,
                              void* d_out, int out_size)
{
    const float* audio = (const float*)d_in[0];
    const float* W     = (const float*)d_in[1];
    const float* bias  = (const float*)d_in[2];
    const float* emb   = (const float*)d_in[3];
    float* out = (float*)d_out;

    // one-time resource setup (no device memory; identical GPU work every call)
    static cudaStream_t s2 = nullptr, s3 = nullptr;
    static cudaEvent_t evFork = nullptr, evJoin = nullptr, evZero = nullptr;
    if (!s2) {
        cudaStreamCreateWithFlags(&s2, cudaStreamNonBlocking);
        cudaStreamCreateWithFlags(&s3, cudaStreamNonBlocking);
        cudaEventCreateWithFlags(&evFork, cudaEventDisableTiming);
        cudaEventCreateWithFlags(&evJoin, cudaEventDisableTiming);
        cudaEventCreateWithFlags(&evZero, cudaEventDisableTiming);
        cudaFuncSetAttribute(mma_gemm<0>, cudaFuncAttributeMaxDynamicSharedMemorySize, SMEMSZ);
        cudaFuncSetAttribute(mma_gemm<1>, cudaFuncAttributeMaxDynamicSharedMemorySize, SMEMSZ);
        cudaFuncSetAttribute(mma_gemm<2>, cudaFuncAttributeMaxDynamicSharedMemorySize, SMEMSZ);
    }

    float *kw, *rowsum;
    __half *audioH, *WH;
    cudaGetSymbolAddress((void**)&kw,     g_kw);
    cudaGetSymbolAddress((void**)&rowsum, g_rowsum);
    cudaGetSymbolAddress((void**)&audioH, g_audioH);
    cudaGetSymbolAddress((void**)&WH,     g_WH);

    // ---- fork ----
    cudaEventRecord(evFork, 0);
    cudaStreamWaitEvent(s2, evFork, 0);
    cudaStreamWaitEvent(s3, evFork, 0);

    // side stream s2: emb prep (longest independent chain)
    emb_prep<<<VV / 16, 512, 0, s2>>>(emb);
    cudaEventRecord(evJoin, s2);

    // side stream s3: all memsets (kw needed by proj; rowsum/out by the GEMMs)
    cudaMemsetAsync(kw,     0, (size_t)BN * TT * sizeof(float), s3);
    cudaMemsetAsync(rowsum, 0, BN * sizeof(float), s3);
    cudaMemsetAsync(out,    0, (size_t)out_size * sizeof(float), s3);
    cudaEventRecord(evZero, s3);

    // main chain: pack -> (wait kw zeroed) proj -> kw_norm
    pack_f16_2<<<304, 512>>>(audio, audioH, BN * DD / 4, W, WH, DD * TT / 4);
    cudaStreamWaitEvent(0, evZero, 0);
    // projection on tensor path: x = n-tiles (4), y = m-tiles (8), z = 6 (nch=2)
    mma_gemm<2><<<dim3(TT / 128, BN / 128, 6), 512, SMEMSZ>>>(kw);
    kw_norm_pack<<<BN / 4, 128>>>(bias);

    // ---- join, then the two floor-bound GEMMs ----
    cudaStreamWaitEvent(0, evJoin, 0);
    // GEMM1: logits + exp epilogue
    mma_gemm<0><<<dim3(BN / 128, VV / 128), 512, SMEMSZ>>>(nullptr);
    // GEMM2: x = n-tiles (4), y = m-tiles (8), z = split-K (9)
    mma_gemm<1><<<dim3(TT / 128, BN / 128, 9), 512, SMEMSZ>>>(out);
}

// round 13
// speedup vs baseline: 1.0051x; 1.0051x over previous
#include <cuda_runtime.h>
#include <cuda_fp16.h>
#include <cstdint>
#include <cstddef>

#define BN 1024
#define DD 768
#define TT 512
#define VV 49408

#define G1_CTAS   296                 // 2 per SM
#define G1_TILES  (8 * (VV / 128))    // 3088
#define PROJ_Z    4

// ------------------------- static device workspace --------------------------
__device__ float g_rowsum[BN];             // softmax denominators (scaled)
__device__ float g_norm[VV];               // ||emb_v|| (fp32)
__device__ float g_kwPart[PROJ_Z][BN * TT];        // proj split-K partials
__device__ __half g_kwH[BN * TT];                  // normalized kw, fp16
__device__ __half g_audioH[BN * DD];               // audio fp16
__device__ __half g_WH[DD * TT];                   // W_proj fp16 [k][n]
__device__ __half g_embH[(size_t)VV * TT];         // NORMALIZED emb [v][t], fp16
__device__ __half g_probs[(size_t)BN * VV];        // scaled probs * ||emb_v||, fp16

// ------------------------------ helpers -------------------------------------
__device__ __forceinline__ uint32_t smem_u32(const void* p) {
    uint32_t a;
    asm("{ .reg .u64 t; cvta.to.shared.u64 t, %1; cvt.u32.u64 %0, t; }"
        : "=r"(a) : "l"(p));
    return a;
}
__device__ __forceinline__ void cp16(uint32_t s, const void* g) {
    asm volatile("cp.async.cg.shared.global [%0], [%1], 16;" :: "r"(s), "l"(g));
}
__device__ __forceinline__ void ldsm4(uint32_t* r, uint32_t addr) {
    asm volatile("ldmatrix.sync.aligned.m8n8.x4.shared.b16 {%0,%1,%2,%3}, [%4];"
        : "=r"(r[0]), "=r"(r[1]), "=r"(r[2]), "=r"(r[3]) : "r"(addr));
}
__device__ __forceinline__ void ldsm4t(uint32_t* r, uint32_t addr) {
    asm volatile("ldmatrix.sync.aligned.m8n8.x4.trans.shared.b16 {%0,%1,%2,%3}, [%4];"
        : "=r"(r[0]), "=r"(r[1]), "=r"(r[2]), "=r"(r[3]) : "r"(addr));
}
__device__ __forceinline__ void mma16816(float* c, const uint32_t* a, const uint32_t* b) {
    asm volatile("mma.sync.aligned.m16n8k16.row.col.f32.f16.f16.f32 "
        "{%0,%1,%2,%3}, {%4,%5,%6,%7}, {%8,%9}, {%0,%1,%2,%3};"
        : "+f"(c[0]), "+f"(c[1]), "+f"(c[2]), "+f"(c[3])
        : "r"(a[0]), "r"(a[1]), "r"(a[2]), "r"(a[3]), "r"(b[0]), "r"(b[1]));
}
__device__ __forceinline__ uint32_t pack2h(float a, float b) {
    const __half2 h = __floats2half2_rn(a, b);
    return *reinterpret_cast<const uint32_t*>(&h);
}

#define ROWA   144
#define ROWBT  272
#define PLANE  18432
#define STAGE  (2 * PLANE)            // 36864
#define NSTAGE 2
#define SMEMSZ (NSTAGE * STAGE + 512) // 74240 -> 2 CTAs/SM

#define PSCALE 16384.f

// =============================================================================
// PERSISTENT GEMM1: logits + exp epilogue. 296 CTAs, each owns 10-11 tiles
// (tile t = bid + 296*i; m0 = (t&7)*128, n0 = (t>>3)*128).
// 2-stage cp.async ring runs continuously across tile boundaries.
// =============================================================================
__global__ __launch_bounds__(512, 2) void gemm1_persist()
{
    extern __shared__ char smem[];
    const uint32_t sbase = smem_u32(smem);
    const int tid = threadIdx.x;
    const int lane = tid & 31, wid = tid >> 5;
    const int warpM = wid & 3, warpN = wid >> 2;
    const int bid = blockIdx.x;
    const int ntiles = (bid < (G1_TILES - (G1_TILES / G1_CTAS) * G1_CTAS))
                     ? (G1_TILES / G1_CTAS + 1) : (G1_TILES / G1_CTAS);
    const int total = ntiles * 8;      // 8 K-chunks per tile (TT/64)

    const uint32_t ch   = tid & 7;
    const uint32_t rowA = tid >> 3;
    const uint32_t aSo = rowA * ROWA + ch * 16;

    auto issue = [&](int s) {
        const int t = bid + (s >> 3) * G1_CTAS;
        const int c = s & 7;
        const uint32_t m0 = (uint32_t)(t & 7) << 7;
        const uint32_t n0 = (uint32_t)(t >> 3) << 7;
        const uint32_t a0 = (m0 + rowA) * TT + (uint32_t)c * 64 + ch * 8;
        const uint32_t b0 = (n0 + rowA) * TT + (uint32_t)c * 64 + ch * 8;
        const uint32_t st = sbase + (uint32_t)(s & 1) * STAGE;
        #pragma unroll
        for (int p = 0; p < 2; p++) {
            cp16(st + aSo + p * (64 * ROWA), g_kwH  + a0 + p * (64 * TT));
            cp16(st + PLANE + aSo + p * (64 * ROWA), g_embH + b0 + p * (64 * TT));
        }
    };

    const uint32_t saOff = (uint32_t)(warpM * 32 + (lane & 15)) * ROWA + ((lane >> 4) << 4);
    const uint32_t sbOff = PLANE + (uint32_t)(warpN * 32 + (lane & 15)) * ROWA
                         + ((lane >> 4) << 4);

    float acc[2][4][4];
    #pragma unroll
    for (int i = 0; i < 2; i++)
        #pragma unroll
        for (int j = 0; j < 4; j++)
            #pragma unroll
            for (int k = 0; k < 4; k++) acc[i][j][k] = 0.f;

    issue(0);
    asm volatile("cp.async.commit_group;" ::: "memory");
    issue(1);
    asm volatile("cp.async.commit_group;" ::: "memory");

    for (int s = 0; s < total; s++) {
        asm volatile("cp.async.wait_group 1;" ::: "memory");
        __syncthreads();
        const uint32_t st = sbase + (uint32_t)(s & 1) * STAGE;

        #pragma unroll
        for (int ks = 0; ks < 4; ks++) {
            const uint32_t ko = ks * 32;
            uint32_t a[2][4], b[2][4];
            #pragma unroll
            for (int mf = 0; mf < 2; mf++)
                ldsm4(a[mf], st + saOff + mf * (16 * ROWA) + ko);
            #pragma unroll
            for (int g = 0; g < 2; g++)
                ldsm4(b[g], st + sbOff + g * (16 * ROWA) + ko);
            #pragma unroll
            for (int mf = 0; mf < 2; mf++)
                #pragma unroll
                for (int nf = 0; nf < 4; nf++) {
                    uint32_t bf[2] = { b[nf >> 1][nf & 1], b[nf >> 1][2 + (nf & 1)] };
                    mma16816(acc[mf][nf], a[mf], bf);
                }
        }
        __syncthreads();
        if (s + 2 < total) issue(s + 2);
        asm volatile("cp.async.commit_group;" ::: "memory");

        if ((s & 7) == 7) {
            // ---- tile epilogue (overlaps with next tile's loads in flight) ----
            const int t = bid + (s >> 3) * G1_CTAS;
            const int m0 = (t & 7) << 7;
            const int n0 = (t >> 3) << 7;
            #pragma unroll
            for (int mf = 0; mf < 2; mf++) {
                const int r0 = m0 + warpM * 32 + mf * 16 + (lane >> 2);
                float rs0 = 0.f, rs1 = 0.f;
                #pragma unroll
                for (int nf = 0; nf < 4; nf++) {
                    const int cb = n0 + warpN * 32 + nf * 8 + (lane & 3) * 2;
                    const float e0 = __expf(acc[mf][nf][0] * 10.f - 10.f) * PSCALE;
                    const float e1 = __expf(acc[mf][nf][1] * 10.f - 10.f) * PSCALE;
                    const float e2 = __expf(acc[mf][nf][2] * 10.f - 10.f) * PSCALE;
                    const float e3 = __expf(acc[mf][nf][3] * 10.f - 10.f) * PSCALE;
                    rs0 += e0 + e1;  rs1 += e2 + e3;
                    const float w0 = __ldg(&g_norm[cb]);
                    const float w1 = __ldg(&g_norm[cb + 1]);
                    *(uint32_t*)&g_probs[(size_t)r0 * VV + cb] = pack2h(e0 * w0, e1 * w1);
                    *(uint32_t*)&g_probs[(size_t)(r0 + 8) * VV + cb] = pack2h(e2 * w0, e3 * w1);
                }
                rs0 += __shfl_xor_sync(0xffffffffu, rs0, 1);
                rs0 += __shfl_xor_sync(0xffffffffu, rs0, 2);
                rs1 += __shfl_xor_sync(0xffffffffu, rs1, 1);
                rs1 += __shfl_xor_sync(0xffffffffu, rs1, 2);
                if ((lane & 3) == 0) {
                    atomicAdd(&g_rowsum[r0],     rs0);
                    atomicAdd(&g_rowsum[r0 + 8], rs1);
                }
            }
            #pragma unroll
            for (int i = 0; i < 2; i++)
                #pragma unroll
                for (int j = 0; j < 4; j++)
                    #pragma unroll
                    for (int k = 0; k < 4; k++) acc[i][j][k] = 0.f;
        }
    }
}

// =============================================================================
// fp16 warp-MMA GEMM (non-persistent), used for GEMM2 and projection.
// EPI==1: VQ GEMM split-K (A=probs, B=embH trans) -> (1/rowsum)*atomicAdd out
// EPI==2: projection split-K (A=audioH, B=WH trans) -> float2 STG to partial z
// =============================================================================
template<int EPI>
__global__ __launch_bounds__(512, 2) void mma_gemm(float* __restrict__ outf)
{
    constexpr uint32_t LDA  = (EPI == 1) ? VV : DD;
    constexpr uint32_t LDB  = TT;
    constexpr int      NCHT = (EPI == 1) ? VV / 64 : DD / 64;
    extern __shared__ char smem[];
    const uint32_t sbase = smem_u32(smem);
    const int tid = threadIdx.x;
    const int lane = tid & 31, wid = tid >> 5;
    const int warpM = wid & 3, warpN = wid >> 2;

    const __half* A = (EPI == 1) ? g_probs : g_audioH;
    const __half* B = (EPI == 1) ? g_embH  : g_WH;
    const int n0 = blockIdx.x * 128, m0 = blockIdx.y * 128;
    const int c0 = (int)(((long)NCHT * blockIdx.z) / gridDim.z);
    const int c1 = (int)(((long)NCHT * (blockIdx.z + 1)) / gridDim.z);
    const int nch = c1 - c0;

    const uint32_t ch   = tid & 7;
    const uint32_t rowA = tid >> 3;
    uint32_t aOff = (uint32_t)(m0 + rowA) * LDA + (uint32_t)c0 * 64 + ch * 8;
    const uint32_t aSo = rowA * ROWA + ch * 16;
    const uint32_t rb = tid >> 4, cb2 = tid & 15;
    uint32_t bOff = ((uint32_t)c0 * 64 + rb) * LDB + (uint32_t)n0 + cb2 * 8;
    const uint32_t bSo = rb * ROWBT + cb2 * 16;

    auto issue = [&](uint32_t st) {
        #pragma unroll
        for (int p = 0; p < 2; p++) {
            cp16(st + aSo + p * (64 * ROWA), A + aOff + p * (64 * LDA));
            cp16(st + PLANE + bSo + p * (32 * ROWBT), B + bOff + p * (32 * LDB));
        }
        aOff += 64;
        bOff += 64 * LDB;
    };

    const uint32_t saOff = (uint32_t)(warpM * 32 + (lane & 15)) * ROWA + ((lane >> 4) << 4);
    const uint32_t sbOff = PLANE + (uint32_t)((lane & 7) + ((lane >> 4) << 3)) * ROWBT
                         + (uint32_t)(warpN * 32 + ((lane >> 3) & 1) * 8) * 2;

    float acc[2][4][4];
    #pragma unroll
    for (int i = 0; i < 2; i++)
        #pragma unroll
        for (int j = 0; j < 4; j++)
            #pragma unroll
            for (int k = 0; k < 4; k++) acc[i][j][k] = 0.f;

    issue(sbase);
    asm volatile("cp.async.commit_group;" ::: "memory");
    issue(sbase + STAGE);
    asm volatile("cp.async.commit_group;" ::: "memory");

    for (int c = 0; c < nch; c++) {
        asm volatile("cp.async.wait_group 1;" ::: "memory");
        __syncthreads();
        const uint32_t st = sbase + (uint32_t)(c & 1) * STAGE;

        #pragma unroll
        for (int ks = 0; ks < 4; ks++) {
            const uint32_t ko = ks * 32;
            uint32_t a[2][4], b[2][4];
            #pragma unroll
            for (int mf = 0; mf < 2; mf++)
                ldsm4(a[mf], st + saOff + mf * (16 * ROWA) + ko);
            #pragma unroll
            for (int g = 0; g < 2; g++)
                ldsm4t(b[g], st + sbOff + ks * (16 * ROWBT) + g * 32);
            #pragma unroll
            for (int mf = 0; mf < 2; mf++)
                #pragma unroll
                for (int nf = 0; nf < 4; nf++) {
                    uint32_t bf[2] = { b[nf >> 1][nf & 1], b[nf >> 1][2 + (nf & 1)] };
                    mma16816(acc[mf][nf], a[mf], bf);
                }
        }
        __syncthreads();
        if (c + 2 < nch) issue(st);
        asm volatile("cp.async.commit_group;" ::: "memory");
    }

    if (EPI == 1) {
        #pragma unroll
        for (int mf = 0; mf < 2; mf++) {
            const int r0 = m0 + warpM * 32 + mf * 16 + (lane >> 2);
            const float s0 = 1.f / g_rowsum[r0];
            const float s1 = 1.f / g_rowsum[r0 + 8];
            #pragma unroll
            for (int nf = 0; nf < 4; nf++) {
                const int cb = n0 + warpN * 32 + nf * 8 + (lane & 3) * 2;
                atomicAdd(&outf[(size_t)r0 * TT + cb],           acc[mf][nf][0] * s0);
                atomicAdd(&outf[(size_t)r0 * TT + cb + 1],       acc[mf][nf][1] * s0);
                atomicAdd(&outf[(size_t)(r0 + 8) * TT + cb],     acc[mf][nf][2] * s1);
                atomicAdd(&outf[(size_t)(r0 + 8) * TT + cb + 1], acc[mf][nf][3] * s1);
            }
        }
    } else {
        // plain float2 stores into this z-chunk's partial buffer (no atomics)
        float* dst = outf + (size_t)blockIdx.z * (BN * TT);
        #pragma unroll
        for (int mf = 0; mf < 2; mf++) {
            const int r0 = m0 + warpM * 32 + mf * 16 + (lane >> 2);
            #pragma unroll
            for (int nf = 0; nf < 4; nf++) {
                const int cb = n0 + warpN * 32 + nf * 8 + (lane & 3) * 2;
                *(float2*)&dst[(size_t)r0 * TT + cb] =
                    make_float2(acc[mf][nf][0], acc[mf][nf][1]);
                *(float2*)&dst[(size_t)(r0 + 8) * TT + cb] =
                    make_float2(acc[mf][nf][2], acc[mf][nf][3]);
            }
        }
    }
}

// fp32 -> fp16 streaming pack, TWO tensors in one launch (audio then W)
__global__ __launch_bounds__(512)
void pack_f16_2(const float* __restrict__ s0, __half* __restrict__ d0, int n0_4,
                const float* __restrict__ s1, __half* __restrict__ d1, int n1_4)
{
    const int total = n0_4 + n1_4;
    for (int i = blockIdx.x * blockDim.x + threadIdx.x; i < total;
         i += gridDim.x * blockDim.x) {
        const float4 v = (i < n0_4) ? ((const float4*)s0)[i]
                                    : ((const float4*)s1)[i - n0_4];
        const uint2 pk = make_uint2(pack2h(v.x, v.y), pack2h(v.z, v.w));
        if (i < n0_4) ((uint2*)d0)[i] = pk;
        else          ((uint2*)d1)[i - n0_4] = pk;
    }
}

// kw rows: sum PROJ_Z split-K partials + bias, L2-normalize, write fp16
__global__ __launch_bounds__(128)
void kw_norm_pack(const float* __restrict__ bias)
{
    const int w    = (blockIdx.x * blockDim.x + threadIdx.x) >> 5;
    const int lane = threadIdx.x & 31;
    if (w >= BN) return;
    const float4* b4 = (const float4*)bias;
    float4 v[4];
    float ss = 0.f;
    #pragma unroll
    for (int q = 0; q < 4; q++) {
        const int i = lane + 32 * q;
        float4 s = b4[i];
        #pragma unroll
        for (int z = 0; z < PROJ_Z; z++) {
            const float4 p = ((const float4*)(g_kwPart[z] + (size_t)w * TT))[i];
            s.x += p.x; s.y += p.y; s.z += p.z; s.w += p.w;
        }
        v[q] = s;
        ss += s.x * s.x + s.y * s.y + s.z * s.z + s.w * s.w;
    }
    #pragma unroll
    for (int o = 16; o > 0; o >>= 1) ss += __shfl_xor_sync(0xffffffffu, ss, o);
    const float inv = 1.f / fmaxf(sqrtf(ss), 1e-8f);
    #pragma unroll
    for (int q = 0; q < 4; q++) {
        const int e0 = (lane + 32 * q) * 4;
        const uint2 pk = make_uint2(pack2h(v[q].x * inv, v[q].y * inv),
                                    pack2h(v[q].z * inv, v[q].w * inv));
        *(uint2*)&g_kwH[(size_t)w * TT + e0] = pk;
    }
}

// emb prep: one warp per vocab row; normalized fp16 (embH) + row norm (g_norm)
__global__ __launch_bounds__(512)
void emb_prep(const float* __restrict__ emb)
{
    const int w    = (blockIdx.x * blockDim.x + threadIdx.x) >> 5;
    const int lane = threadIdx.x & 31;
    if (w >= VV) return;
    const float4* row = (const float4*)(emb + (size_t)w * TT);
    float4 v[4];
    float ss = 0.f;
    #pragma unroll
    for (int q = 0; q < 4; q++) {
        v[q] = row[lane + 32 * q];
        ss += v[q].x * v[q].x + v[q].y * v[q].y + v[q].z * v[q].z + v[q].w * v[q].w;
    }
    #pragma unroll
    for (int o = 16; o > 0; o >>= 1) ss += __shfl_xor_sync(0xffffffffu, ss, o);
    const float nrm = sqrtf(ss);
    const float inv = 1.f / fmaxf(nrm, 1e-8f);
    if (lane == 0) g_norm[w] = nrm;
    #pragma unroll
    for (int q = 0; q < 4; q++) {
        const int e0 = (lane + 32 * q) * 4;
        const uint2 pk = make_uint2(pack2h(v[q].x * inv, v[q].y * inv),
                                    pack2h(v[q].z * inv, v[q].w * inv));
        *(uint2*)&g_embH[(size_t)w * TT + e0] = pk;
    }
}

// =============================================================================
extern "C" void kernel_launch(void* const* d_in, const int* in_sizes, int n_in,
                              void* d_out, int out_size)
{
    const float* audio = (const float*)d_in[0];
    const float* W     = (const float*)d_in[1];
    const float* bias  = (const float*)d_in[2];
    const float* emb   = (const float*)d_in[3];
    float* out = (float*)d_out;

    static cudaStream_t s2 = nullptr, s3 = nullptr;
    static cudaEvent_t evFork = nullptr, evJoin = nullptr, evZero = nullptr;
    if (!s2) {
        cudaStreamCreateWithFlags(&s2, cudaStreamNonBlocking);
        cudaStreamCreateWithFlags(&s3, cudaStreamNonBlocking);
        cudaEventCreateWithFlags(&evFork, cudaEventDisableTiming);
        cudaEventCreateWithFlags(&evJoin, cudaEventDisableTiming);
        cudaEventCreateWithFlags(&evZero, cudaEventDisableTiming);
        cudaFuncSetAttribute(gemm1_persist, cudaFuncAttributeMaxDynamicSharedMemorySize, SMEMSZ);
        cudaFuncSetAttribute(mma_gemm<1>, cudaFuncAttributeMaxDynamicSharedMemorySize, SMEMSZ);
        cudaFuncSetAttribute(mma_gemm<2>, cudaFuncAttributeMaxDynamicSharedMemorySize, SMEMSZ);
    }

    float *rowsum, *kwPart;
    __half *audioH, *WH;
    cudaGetSymbolAddress((void**)&rowsum, g_rowsum);
    cudaGetSymbolAddress((void**)&kwPart, g_kwPart);
    cudaGetSymbolAddress((void**)&audioH, g_audioH);
    cudaGetSymbolAddress((void**)&WH,     g_WH);

    // ---- fork ----
    cudaEventRecord(evFork, 0);
    cudaStreamWaitEvent(s2, evFork, 0);
    cudaStreamWaitEvent(s3, evFork, 0);

    // side stream s2: emb prep (longest independent chain)
    emb_prep<<<VV / 16, 512, 0, s2>>>(emb);
    cudaEventRecord(evJoin, s2);

    // side stream s3: memsets needed by the GEMMs (not by proj anymore)
    cudaMemsetAsync(rowsum, 0, BN * sizeof(float), s3);
    cudaMemsetAsync(out,    0, (size_t)out_size * sizeof(float), s3);
    cudaEventRecord(evZero, s3);

    // main chain: pack -> proj (atomic-free split-K) -> kw_norm
    pack_f16_2<<<304, 512>>>(audio, audioH, BN * DD / 4, W, WH, DD * TT / 4);
    mma_gemm<2><<<dim3(TT / 128, BN / 128, PROJ_Z), 512, SMEMSZ>>>(kwPart);
    kw_norm_pack<<<BN / 4, 128>>>(bias);

    // ---- join, then the two floor-bound GEMMs ----
    cudaStreamWaitEvent(0, evJoin, 0);
    cudaStreamWaitEvent(0, evZero, 0);
    // GEMM1: persistent, 296 CTAs
    gemm1_persist<<<G1_CTAS, 512, SMEMSZ>>>();
    // GEMM2: x = n-tiles (4), y = m-tiles (8), z = split-K (9)
    mma_gemm<1><<<dim3(TT / 128, BN / 128, 9), 512, SMEMSZ>>>(out);
}